// round 5
// baseline (speedup 1.0000x reference)
#include <cuda_runtime.h>
#include <cuda.h>
#include <cuda_bf16.h>
#include <cstdint>

// ============================================================
// Problem constants
// ============================================================
constexpr int N_ROWS = 4096;
constexpr int D_DIM  = 768;
constexpr float FP8_SCALE = 64.0f;                       // input scaling
constexpr float LOGIT_SCALE = 20.0f / (FP8_SCALE * FP8_SCALE);  // 1/T / s^2

constexpr int BM = 128;          // anchor rows per CTA
constexpr int BN = 256;          // positive rows per CTA
constexpr int BK = 128;          // K chunk (128 e4m3 = 128B = SW128 row)
constexpr int MT = N_ROWS / BM;  // 32
constexpr int NT = N_ROWS / BN;  // 16
constexpr int NKC = D_DIM / BK;  // 6
constexpr int THREADS = 512;     // 16 warps: 4 (M) x 4 (N)
constexpr int STAGES = 4;

constexpr int A_BYTES = BM * 128;              // 16384
constexpr int B_BYTES = BN * 128;              // 32768
constexpr int STAGE_BYTES = A_BYTES + B_BYTES; // 49152
constexpr int SMEM_TOTAL = 1024 + STAGES * STAGE_BYTES;  // 197632

// ============================================================
// Device scratch (static — no allocation)
// ============================================================
__device__ uint8_t g_A[N_ROWS * D_DIM];   // e4m3, scaled by 64
__device__ uint8_t g_B[N_ROWS * D_DIM];   // e4m3, scaled by 64
__device__ float g_partials[NT * N_ROWS];
__device__ float g_last[N_ROWS];

// ============================================================
// Helpers
// ============================================================
__device__ __forceinline__ uint32_t smem_to_u32(const void* smem_ptr) {
    uint32_t addr;
    asm("{ .reg .u64 tmp; cvta.to.shared.u64 tmp, %1; cvt.u32.u64 %0, tmp; }"
        : "=r"(addr) : "l"(smem_ptr));
    return addr;
}

__device__ __forceinline__ uint32_t sw128(uint32_t off) {
    return off ^ ((off >> 3) & 0x70);
}

__device__ __forceinline__ void ldmatrix_x4(uint32_t* r, uint32_t addr) {
    asm volatile("ldmatrix.sync.aligned.m8n8.x4.shared.b16 {%0,%1,%2,%3}, [%4];"
                 : "=r"(r[0]), "=r"(r[1]), "=r"(r[2]), "=r"(r[3]) : "r"(addr));
}

// fp8 e4m3 MMA: m16n8k32, f32 accum. Fragment byte layout identical to
// bf16 m16n8k16 (4 consecutive K-bytes per lane per 8x16B block), so the
// same ldmatrix addressing feeds it.
__device__ __forceinline__ void mma_fp8(float* c, const uint32_t* a,
                                        const uint32_t* b) {
    asm volatile(
        "mma.sync.aligned.m16n8k32.row.col.f32.e4m3.e4m3.f32 "
        "{%0,%1,%2,%3}, {%4,%5,%6,%7}, {%8,%9}, {%0,%1,%2,%3};"
        : "+f"(c[0]), "+f"(c[1]), "+f"(c[2]), "+f"(c[3])
        : "r"(a[0]), "r"(a[1]), "r"(a[2]), "r"(a[3]), "r"(b[0]), "r"(b[1]));
}

// Pack 4 floats -> 4 e4m3 bytes (f0 = lowest byte)
__device__ __forceinline__ uint32_t pack_e4m3x4(float f0, float f1,
                                                float f2, float f3) {
    uint16_t lo, hi;
    asm("cvt.rn.satfinite.e4m3x2.f32 %0, %1, %2;" : "=h"(lo) : "f"(f1), "f"(f0));
    asm("cvt.rn.satfinite.e4m3x2.f32 %0, %1, %2;" : "=h"(hi) : "f"(f3), "f"(f2));
    return (uint32_t)lo | ((uint32_t)hi << 16);
}

#define MBARRIER_INIT(mbar, count) \
    asm volatile("mbarrier.init.shared.b64 [%0], %1;" \
                 :: "r"((uint32_t)(mbar)), "r"((uint32_t)(count)) : "memory")

#define MBARRIER_EXPECT_TX(mbar, bytes) \
    asm volatile("mbarrier.arrive.expect_tx.shared.b64 _, [%0], %1;" \
                 :: "r"((uint32_t)(mbar)), "r"((uint32_t)(bytes)) : "memory")

#define MBARRIER_ARRIVE(mbar) \
    asm volatile("mbarrier.arrive.shared.b64 _, [%0];" \
                 :: "r"((uint32_t)(mbar)) : "memory")

#define MBARRIER_WAIT_PARITY(mbar, parity) do { \
    uint32_t _mbar = (uint32_t)(mbar); \
    uint32_t _parity = (uint32_t)(parity); \
    uint32_t _done; \
    asm volatile( \
        "{\n\t" \
        ".reg .pred p;\n\t" \
        "mbarrier.try_wait.parity.acquire.cta.shared::cta.b64 p, [%1], %2;\n\t" \
        "selp.b32 %0, 1, 0, p;\n\t" \
        "}" \
        : "=r"(_done) : "r"(_mbar), "r"(_parity) : "memory"); \
    if (!_done) { \
        asm volatile( \
            "{\n\t" \
            ".reg .pred P1;\n\t" \
            "WAIT_LOOP_%=:\n\t" \
            "mbarrier.try_wait.parity.acquire.cta.shared::cta.b64 P1, [%0], %1, 0x989680;\n\t" \
            "@P1 bra.uni WAIT_DONE_%=;\n\t" \
            "bra.uni WAIT_LOOP_%=;\n\t" \
            "WAIT_DONE_%=:\n\t" \
            "}" \
            :: "r"(_mbar), "r"(_parity) : "memory"); \
    } \
} while(0)

#define TMA_LOAD_2D(smem_addr, tmap_ptr, cx, cy, mbar) \
    asm volatile( \
        "cp.async.bulk.tensor.2d.shared::cta.global.tile.mbarrier::complete_tx::bytes " \
        "[%0], [%1, {%2, %3}], [%4];" \
        :: "r"((uint32_t)(smem_addr)), "l"(tmap_ptr), \
           "r"((int)(cx)), "r"((int)(cy)), "r"((uint32_t)(mbar)) \
        : "memory")

// ============================================================
// Kernel 1: f32 -> e4m3 conversion (scaled by 64)
// ============================================================
__global__ void convert_kernel(const float* __restrict__ anchors,
                               const float* __restrict__ positives) {
    constexpr int HALF4 = N_ROWS * D_DIM / 8;  // float4 count per half
    int i = blockIdx.x * blockDim.x + threadIdx.x;
    #pragma unroll
    for (int h = 0; h < 2; ++h) {
        int idx = i + h * HALF4;
        float4 a = reinterpret_cast<const float4*>(anchors)[idx];
        float4 p = reinterpret_cast<const float4*>(positives)[idx];
        reinterpret_cast<uint32_t*>(g_A)[idx] =
            pack_e4m3x4(a.x * FP8_SCALE, a.y * FP8_SCALE,
                        a.z * FP8_SCALE, a.w * FP8_SCALE);
        reinterpret_cast<uint32_t*>(g_B)[idx] =
            pack_e4m3x4(p.x * FP8_SCALE, p.y * FP8_SCALE,
                        p.z * FP8_SCALE, p.w * FP8_SCALE);
    }
}

// ============================================================
// Kernel 2: TMA-fed fp8 MMA GEMM fused with row exp-sum
// CTA (nt, mt): logits tile rows [mt*128,+128) x cols [nt*256,+256)
// SMEM: [0,32) full mbarriers, [64,96) empty mbarriers, tiles from 1024
// ============================================================
__global__ void __launch_bounds__(THREADS, 1)
gemm_epilogue_kernel(const __grid_constant__ CUtensorMap tmA,
                     const __grid_constant__ CUtensorMap tmB) {
    extern __shared__ char smem[];
    const int tid = threadIdx.x;
    const int lane = tid & 31;
    const int wid = tid >> 5;
    const int warpM = wid & 3;   // 0..3 -> 32-row band
    const int warpN = wid >> 2;  // 0..3 -> 64-col band
    const int nt = blockIdx.x;
    const int mt = blockIdx.y;
    const uint32_t sb = smem_to_u32(smem);

    auto full_bar  = [&](int s) { return sb + s * 8; };
    auto empty_bar = [&](int s) { return sb + 64 + s * 8; };
    auto stage_off = [&](int s) { return sb + 1024 + (uint32_t)s * STAGE_BYTES; };

    if (tid == 0) {
        #pragma unroll
        for (int s = 0; s < STAGES; ++s) {
            MBARRIER_INIT(full_bar(s), 1);
            MBARRIER_INIT(empty_bar(s), THREADS);
        }
        asm volatile("fence.proxy.async.shared::cta;" ::: "memory");
    }
    __syncthreads();

    // Prologue: fill first STAGES chunks (NKC=6 > STAGES=4)
    if (tid == 0) {
        #pragma unroll
        for (int s = 0; s < STAGES; ++s) {
            MBARRIER_EXPECT_TX(full_bar(s), STAGE_BYTES);
            TMA_LOAD_2D(stage_off(s),           &tmA, s * BK, mt * BM, full_bar(s));
            TMA_LOAD_2D(stage_off(s) + A_BYTES, &tmB, s * BK, nt * BN, full_bar(s));
        }
    }

    float acc[16][4];
    #pragma unroll
    for (int i = 0; i < 16; ++i)
        #pragma unroll
        for (int j = 0; j < 4; ++j) acc[i][j] = 0.0f;

    // Fragment smem offsets (stage-relative, byte-identical to bf16 case)
    const uint32_t a_row = (uint32_t)(warpM * 32 + (lane & 15));
    const uint32_t a_kb  = (uint32_t)((lane >> 4) * 16);
    const uint32_t b_row = (uint32_t)(warpN * 64 + ((lane & 7) | ((lane >> 4) << 3)));
    const uint32_t b_kb  = (uint32_t)(((lane >> 3) & 1) * 16);

    for (int c = 0; c < NKC; ++c) {
        const int s = c & (STAGES - 1);
        const int ph = (c >> 2) & 1;
        MBARRIER_WAIT_PARITY(full_bar(s), ph);

        const uint32_t sA = stage_off(s);
        const uint32_t sB = sA + A_BYTES;

        // 4 K-steps of 32 e4m3 each (32 bytes) cover the 128B row
        #pragma unroll
        for (int ks = 0; ks < 4; ++ks) {
            uint32_t a[2][4];
            #pragma unroll
            for (int mi = 0; mi < 2; ++mi) {
                uint32_t off = (a_row + mi * 16) * 128 + ks * 32 + a_kb;
                ldmatrix_x4(a[mi], sA + sw128(off));
            }
            uint32_t b[4][4];
            #pragma unroll
            for (int np = 0; np < 4; ++np) {
                uint32_t off = (b_row + np * 16) * 128 + ks * 32 + b_kb;
                ldmatrix_x4(b[np], sB + sw128(off));
            }
            #pragma unroll
            for (int mi = 0; mi < 2; ++mi)
                #pragma unroll
                for (int ni = 0; ni < 8; ++ni)
                    mma_fp8(acc[mi * 8 + ni], a[mi], &b[ni >> 1][(ni & 1) * 2]);
        }

        MBARRIER_ARRIVE(empty_bar(s));

        // Producer: refill slot s with chunk c+STAGES once drained
        if (tid == 0 && c + STAGES < NKC) {
            MBARRIER_WAIT_PARITY(empty_bar(s), ph);
            MBARRIER_EXPECT_TX(full_bar(s), STAGE_BYTES);
            TMA_LOAD_2D(stage_off(s),           &tmA, (c + STAGES) * BK, mt * BM,
                        full_bar(s));
            TMA_LOAD_2D(stage_off(s) + A_BYTES, &tmB, (c + STAGES) * BK, nt * BN,
                        full_bar(s));
        }
    }

    // ---- Fused epilogue: exp, diagonal, last-col, row reduction ----
    __syncthreads();
    float* rowsum = reinterpret_cast<float*>(smem + 1024);  // reuse tile smem
    if (tid < BM) rowsum[tid] = 0.0f;
    __syncthreads();

    #pragma unroll
    for (int mi = 0; mi < 2; ++mi) {
        #pragma unroll
        for (int h = 0; h < 2; ++h) {
            const int lr = warpM * 32 + mi * 16 + h * 8 + (lane >> 2);
            const int grow = mt * BM + lr;
            float rs = 0.0f;
            #pragma unroll
            for (int ni = 0; ni < 8; ++ni) {
                #pragma unroll
                for (int j = 0; j < 2; ++j) {
                    float v = acc[mi * 8 + ni][h * 2 + j] * LOGIT_SCALE;
                    int gcol = nt * BN + warpN * 64 + ni * 8 + (lane & 3) * 2 + j;
                    float e = __expf(v);
                    rs += e;
                    if (gcol == grow) rs += e;           // diagonal double-count
                    if (gcol == N_ROWS - 1) g_last[grow] = v;
                }
            }
            atomicAdd(&rowsum[lr], rs);
        }
    }
    __syncthreads();
    if (tid < BM)
        g_partials[nt * N_ROWS + mt * BM + tid] = rowsum[tid];
}

// ============================================================
// Kernel 3: deterministic finalize (single block)
// ============================================================
__global__ void __launch_bounds__(1024)
finalize_kernel(float* __restrict__ out) {
    __shared__ float red[1024];
    const int t = threadIdx.x;
    float acc = 0.0f;
    for (int r = t; r < N_ROWS; r += 1024) {
        float denom = 0.0f;
        #pragma unroll
        for (int n = 0; n < NT; ++n)
            denom += g_partials[n * N_ROWS + r];
        acc += logf(denom) - g_last[r];  // loss_r = log(denom) - logits[r,-1]
    }
    red[t] = acc;
    __syncthreads();
    #pragma unroll
    for (int s = 512; s > 0; s >>= 1) {
        if (t < s) red[t] += red[t + s];
        __syncthreads();
    }
    if (t == 0) out[0] = red[0];
}

// ============================================================
// Launch
// ============================================================
typedef CUresult (*EncodeTiledFn)(
    CUtensorMap*, CUtensorMapDataType, cuuint32_t, void*,
    const cuuint64_t*, const cuuint64_t*, const cuuint32_t*, const cuuint32_t*,
    CUtensorMapInterleave, CUtensorMapSwizzle, CUtensorMapL2promotion,
    CUtensorMapFloatOOBfill);

extern "C" void kernel_launch(void* const* d_in, const int* in_sizes, int n_in,
                              void* d_out, int out_size) {
    const float* anchors   = (const float*)d_in[0];
    const float* positives = (const float*)d_in[1];
    float* out = (float*)d_out;

    void* fn = nullptr;
    cudaDriverEntryPointQueryResult qr;
    cudaGetDriverEntryPointByVersion("cuTensorMapEncodeTiled", &fn, 12000,
                                     cudaEnableDefault, &qr);
    EncodeTiledFn encode = (EncodeTiledFn)fn;

    void* pA = nullptr;
    void* pB = nullptr;
    cudaGetSymbolAddress(&pA, g_A);
    cudaGetSymbolAddress(&pB, g_B);

    CUtensorMap tmA, tmB;
    cuuint64_t dims[2]    = {(cuuint64_t)D_DIM, (cuuint64_t)N_ROWS};
    cuuint64_t strides[1] = {(cuuint64_t)D_DIM};  // 1 byte per e4m3
    cuuint32_t es[2]      = {1, 1};
    cuuint32_t boxA[2]    = {(cuuint32_t)BK, (cuuint32_t)BM};
    cuuint32_t boxB[2]    = {(cuuint32_t)BK, (cuuint32_t)BN};
    encode(&tmA, CU_TENSOR_MAP_DATA_TYPE_UINT8, 2, pA, dims, strides, boxA,
           es, CU_TENSOR_MAP_INTERLEAVE_NONE, CU_TENSOR_MAP_SWIZZLE_128B,
           CU_TENSOR_MAP_L2_PROMOTION_L2_128B, CU_TENSOR_MAP_FLOAT_OOB_FILL_NONE);
    encode(&tmB, CU_TENSOR_MAP_DATA_TYPE_UINT8, 2, pB, dims, strides, boxB,
           es, CU_TENSOR_MAP_INTERLEAVE_NONE, CU_TENSOR_MAP_SWIZZLE_128B,
           CU_TENSOR_MAP_L2_PROMOTION_L2_128B, CU_TENSOR_MAP_FLOAT_OOB_FILL_NONE);

    cudaFuncSetAttribute(gemm_epilogue_kernel,
                         cudaFuncAttributeMaxDynamicSharedMemorySize, SMEM_TOTAL);

    constexpr int HALF4 = N_ROWS * D_DIM / 8;
    convert_kernel<<<HALF4 / 256, 256>>>(anchors, positives);

    dim3 grid(NT, MT);
    gemm_epilogue_kernel<<<grid, THREADS, SMEM_TOTAL>>>(tmA, tmB);

    finalize_kernel<<<1, 1024>>>(out);
}